// round 10
// baseline (speedup 1.0000x reference)
#include <cuda_runtime.h>
#include <cstdint>

#define N_NODES 100000
#define N_EDGES 1600000
#define D_IN 128
#define D_HID 128
#define D_OUTD 64

#define SCAN_B 1024
#define NBLK ((N_NODES + SCAN_B - 1) / SCAN_B)   // 98

// ---------------- scratch (device globals; no allocation) ----------------
__device__ float g_Y1[N_NODES * D_HID];    // X @ W_l1^T
__device__ float g_Z1[N_NODES * D_HID];    // X @ W_r1^T + b1
__device__ float g_H[N_NODES * D_HID];     // layer-1 output (post relu)
__device__ float g_Y2[N_NODES * D_OUTD];   // H @ W_l2^T
__device__ float g_Z2[N_NODES * D_OUTD];   // H @ W_r2^T + b2
__device__ int   g_deg[N_NODES];
__device__ int   g_row_ptr[N_NODES + 1];
__device__ int   g_cursor[N_NODES];
__device__ int   g_csr_src[N_EDGES];
__device__ int   g_blocksum[NBLK];
__device__ int   g_boff[NBLK];
__device__ int   g_total;
__device__ int   g_is64;                   // 1 if edge_index is int64, 0 if int32

// ---------------- dtype probe ----------------
__global__ void detect_kernel(const int* __restrict__ ei) {
    int all_zero = 1;
    for (int i = 0; i < 128; i++) {
        if (ei[2 * i + 1] != 0) { all_zero = 0; break; }
    }
    g_is64 = all_zero;
}

__device__ __forceinline__ int edge_at(const int* ei, int idx, int is64) {
    return is64 ? (int)((const long long*)ei)[idx] : ei[idx];
}

// ---------------- degree histogram ----------------
__global__ void zero_deg_kernel() {
    int i = blockIdx.x * blockDim.x + threadIdx.x;
    if (i < N_NODES) g_deg[i] = 0;
}

__global__ void deg_kernel(const int* __restrict__ ei) {
    int e = blockIdx.x * blockDim.x + threadIdx.x;
    if (e < N_EDGES) {
        int is64 = g_is64;
        int dst = edge_at(ei, N_EDGES + e, is64);
        if ((unsigned)dst < N_NODES) atomicAdd(&g_deg[dst], 1);
    }
}

// ---------------- 3-phase exclusive scan ----------------
__global__ __launch_bounds__(SCAN_B) void scanA_kernel() {
    __shared__ int s[SCAN_B];
    int t = threadIdx.x;
    int i = blockIdx.x * SCAN_B + t;
    int v = (i < N_NODES) ? g_deg[i] : 0;
    s[t] = v;
    __syncthreads();
    for (int off = 1; off < SCAN_B; off <<= 1) {
        int u = (t >= off) ? s[t - off] : 0;
        __syncthreads();
        s[t] += u;
        __syncthreads();
    }
    if (i < N_NODES) g_row_ptr[i] = s[t] - v;
    if (t == SCAN_B - 1) g_blocksum[blockIdx.x] = s[t];
}

__global__ __launch_bounds__(128) void scanB_kernel() {
    __shared__ int s[128];
    int t = threadIdx.x;
    int v = (t < NBLK) ? g_blocksum[t] : 0;
    s[t] = v;
    __syncthreads();
    for (int off = 1; off < 128; off <<= 1) {
        int u = (t >= off) ? s[t - off] : 0;
        __syncthreads();
        s[t] += u;
        __syncthreads();
    }
    if (t < NBLK) g_boff[t] = s[t] - v;
    if (t == 127) g_total = s[127];
}

__global__ __launch_bounds__(SCAN_B) void scanC_kernel() {
    int i = blockIdx.x * SCAN_B + threadIdx.x;
    if (i < N_NODES) {
        int r = g_row_ptr[i] + g_boff[blockIdx.x];
        g_row_ptr[i] = r;
        g_cursor[i] = r;
    }
    if (i == 0) g_row_ptr[N_NODES] = g_total;
}

// ---------------- CSR fill ----------------
__global__ void fill_kernel(const int* __restrict__ ei) {
    int e = blockIdx.x * blockDim.x + threadIdx.x;
    if (e >= N_EDGES) return;
    int is64 = g_is64;
    int src = edge_at(ei, e, is64);
    int dst = edge_at(ei, N_EDGES + e, is64);
    if ((unsigned)src >= N_NODES || (unsigned)dst >= N_NODES) return;
    int pos = atomicAdd(&g_cursor[dst], 1);
    g_csr_src[pos] = src;
}

// ---------------- tf32 helpers ----------------
__device__ __forceinline__ uint32_t f2tf(float x) {
    uint32_t r;
    asm("cvt.rna.tf32.f32 %0, %1;" : "=r"(r) : "f"(x));
    return r;
}

__device__ __forceinline__ void mma8(float* d, const uint32_t* a, const uint32_t* b) {
    asm volatile(
        "mma.sync.aligned.m16n8k8.row.col.f32.tf32.tf32.f32 "
        "{%0,%1,%2,%3}, {%4,%5,%6,%7}, {%8,%9}, {%0,%1,%2,%3};"
        : "+f"(d[0]), "+f"(d[1]), "+f"(d[2]), "+f"(d[3])
        : "r"(a[0]), "r"(a[1]), "r"(a[2]), "r"(a[3]), "r"(b[0]), "r"(b[1]));
}

// split x -> (hi, lo) both as tf32 bit patterns stored in float slots
__device__ __forceinline__ void split_pair(float c0, float c4, float4& out) {
    uint32_t h0 = f2tf(c0), h4 = f2tf(c4);
    float l0 = c0 - __uint_as_float(h0);
    float l4 = c4 - __uint_as_float(h4);
    out = make_float4(__uint_as_float(h0), __uint_as_float(h4),
                      __uint_as_float(f2tf(l0)), __uint_as_float(f2tf(l4)));
}

// ---------------- tensor-core fused dual GEMM (3xTF32 split) ----------------
// C = X[N,128] @ Wcat[2*DOUT,128]^T.  TM=128 x TN=128 tile, 8 warps (4x2),
// each warp 32x64 via 2x8 m16n8k8 fragments. K staged in 16-col chunks.
// smem layout (per k8-block kb, row r, quad kq): float4 =
//   (hi(x[r][kq]), hi(x[r][kq+4]), lo(x[r][kq]), lo(x[r][kq+4]))
// so one LDS.128 delivers a thread's hi AND lo fragment elements.
template <int LAYER>
__global__ __launch_bounds__(256) void gemm_tc(const float* __restrict__ Xin,
                                               const float* __restrict__ Wl,
                                               const float* __restrict__ Wr,
                                               const float* __restrict__ bias) {
    constexpr int DOUT = (LAYER == 1) ? D_HID : D_OUTD;
    constexpr int K = 128, TM = 128;

    const float* X = (LAYER == 1) ? Xin : g_H;
    float* Y = (LAYER == 1) ? g_Y1 : g_Y2;
    float* Z = (LAYER == 1) ? g_Z1 : g_Z2;

    __shared__ float4 Xs4[2][128][4];   // 16 KB
    __shared__ float4 Ws4[2][128][4];   // 16 KB

    const int tid = threadIdx.x;
    const int lane = tid & 31;
    const int wid = tid >> 5;           // 0..7
    const int wm = wid >> 1;            // 0..3 -> rows wm*32
    const int wn = wid & 1;             // 0..1 -> cols wn*64
    const int m0 = blockIdx.x * TM;
    const int n0 = blockIdx.y * TM;     // concat col base

    // loader mapping: 256 threads -> 128 rows x 2 k8-blocks
    const int lrow = tid >> 1;
    const int lkb = tid & 1;

    int mrow = m0 + lrow; if (mrow >= N_NODES) mrow = N_NODES - 1;
    const float* xrow = X + (size_t)mrow * K + lkb * 8;

    const int cr = n0 + lrow;
    const float* wrow = ((cr < DOUT) ? (Wl + (size_t)cr * K)
                                     : (Wr + (size_t)(cr - DOUT) * K)) + lkb * 8;

    float acc[2][8][4] = {};

    for (int k0 = 0; k0 < K; k0 += 16) {
        __syncthreads();
        {
            float4 v0 = *(const float4*)(xrow + k0);
            float4 v1 = *(const float4*)(xrow + k0 + 4);
            split_pair(v0.x, v1.x, Xs4[lkb][lrow][0]);
            split_pair(v0.y, v1.y, Xs4[lkb][lrow][1]);
            split_pair(v0.z, v1.z, Xs4[lkb][lrow][2]);
            split_pair(v0.w, v1.w, Xs4[lkb][lrow][3]);
            float4 w0 = *(const float4*)(wrow + k0);
            float4 w1 = *(const float4*)(wrow + k0 + 4);
            split_pair(w0.x, w1.x, Ws4[lkb][lrow][0]);
            split_pair(w0.y, w1.y, Ws4[lkb][lrow][1]);
            split_pair(w0.z, w1.z, Ws4[lkb][lrow][2]);
            split_pair(w0.w, w1.w, Ws4[lkb][lrow][3]);
        }
        __syncthreads();

#pragma unroll
        for (int kb = 0; kb < 2; kb++) {
            // A fragments (hi+lo) for this warp's two m16 blocks
            uint32_t ahi[2][4], alo[2][4];
#pragma unroll
            for (int mf = 0; mf < 2; mf++) {
                int rbase = wm * 32 + mf * 16 + (lane >> 2);
                float4 A1 = Xs4[kb][rbase][lane & 3];       // rows 0..7  -> a0,a2
                float4 A2 = Xs4[kb][rbase + 8][lane & 3];   // rows 8..15 -> a1,a3
                ahi[mf][0] = __float_as_uint(A1.x); ahi[mf][1] = __float_as_uint(A2.x);
                ahi[mf][2] = __float_as_uint(A1.y); ahi[mf][3] = __float_as_uint(A2.y);
                alo[mf][0] = __float_as_uint(A1.z); alo[mf][1] = __float_as_uint(A2.z);
                alo[mf][2] = __float_as_uint(A1.w); alo[mf][3] = __float_as_uint(A2.w);
            }
#pragma unroll
            for (int nf = 0; nf < 8; nf++) {
                int cbase = wn * 64 + nf * 8 + (lane >> 2);
                float4 Bv = Ws4[kb][cbase][lane & 3];
                uint32_t bhi[2] = {__float_as_uint(Bv.x), __float_as_uint(Bv.y)};
                uint32_t blo[2] = {__float_as_uint(Bv.z), __float_as_uint(Bv.w)};
#pragma unroll
                for (int mf = 0; mf < 2; mf++) {
                    mma8(acc[mf][nf], ahi[mf], bhi);
                    mma8(acc[mf][nf], ahi[mf], blo);
                    mma8(acc[mf][nf], alo[mf], bhi);
                }
            }
        }
    }

    // epilogue
#pragma unroll
    for (int mf = 0; mf < 2; mf++) {
#pragma unroll
        for (int nf = 0; nf < 8; nf++) {
            int r0 = m0 + wm * 32 + mf * 16 + (lane >> 2);
            int ccol = n0 + wn * 64 + nf * 8 + 2 * (lane & 3);
            bool isZ = (ccol >= DOUT);
            int col = isZ ? (ccol - DOUT) : ccol;
            float* base = isZ ? Z : Y;
            float b0 = isZ ? bias[col] : 0.0f;
            float b1 = isZ ? bias[col + 1] : 0.0f;
            const float* a = acc[mf][nf];
            if (r0 < N_NODES) {
                float2 v = make_float2(a[0] + b0, a[1] + b1);
                *(float2*)(base + (size_t)r0 * DOUT + col) = v;
            }
            if (r0 + 8 < N_NODES) {
                float2 v = make_float2(a[2] + b0, a[3] + b1);
                *(float2*)(base + (size_t)(r0 + 8) * DOUT + col) = v;
            }
        }
    }
}

// ---------------- warp-per-node gather + mean + Z (+relu) ----------------
template <int LAYER>
__global__ __launch_bounds__(256) void agg_kernel(float* __restrict__ OutArg) {
    constexpr int D = (LAYER == 1) ? D_HID : D_OUTD;
    constexpr bool RELU = (LAYER == 1);
    const float* __restrict__ Y = (LAYER == 1) ? g_Y1 : g_Y2;
    const float* __restrict__ Z = (LAYER == 1) ? g_Z1 : g_Z2;
    const int* __restrict__ rp = g_row_ptr;
    const int* __restrict__ cs = g_csr_src;
    float* O = (LAYER == 1) ? g_H : OutArg;

    int warp = (blockIdx.x * blockDim.x + threadIdx.x) >> 5;
    if (warp >= N_NODES) return;
    int lane = threadIdx.x & 31;

    int beg = __ldg(&rp[warp]);
    int end = __ldg(&rp[warp + 1]);
    int deg = end - beg;

    if (D == 128) {
        float4 acc = make_float4(0.f, 0.f, 0.f, 0.f);
        for (int j0 = beg; j0 < end; j0 += 32) {
            int my = (j0 + lane < end) ? __ldg(&cs[j0 + lane]) : 0;
            int cnt = min(32, end - j0);
            for (int t = 0; t < cnt; t++) {
                int s = __shfl_sync(0xffffffffu, my, t);
                float4 v = __ldg((const float4*)(Y + (size_t)s * D + lane * 4));
                acc.x += v.x; acc.y += v.y; acc.z += v.z; acc.w += v.w;
            }
        }
        float inv = 1.0f / fmaxf((float)deg, 1.0f);
        float4 z = __ldg((const float4*)(Z + (size_t)warp * D + lane * 4));
        float4 r = make_float4(fmaf(acc.x, inv, z.x), fmaf(acc.y, inv, z.y),
                               fmaf(acc.z, inv, z.z), fmaf(acc.w, inv, z.w));
        if (RELU) {
            r.x = fmaxf(r.x, 0.f); r.y = fmaxf(r.y, 0.f);
            r.z = fmaxf(r.z, 0.f); r.w = fmaxf(r.w, 0.f);
        }
        *(float4*)(O + (size_t)warp * D + lane * 4) = r;
    } else {
        float2 acc = make_float2(0.f, 0.f);
        for (int j0 = beg; j0 < end; j0 += 32) {
            int my = (j0 + lane < end) ? __ldg(&cs[j0 + lane]) : 0;
            int cnt = min(32, end - j0);
            for (int t = 0; t < cnt; t++) {
                int s = __shfl_sync(0xffffffffu, my, t);
                float2 v = __ldg((const float2*)(Y + (size_t)s * D + lane * 2));
                acc.x += v.x; acc.y += v.y;
            }
        }
        float inv = 1.0f / fmaxf((float)deg, 1.0f);
        float2 z = __ldg((const float2*)(Z + (size_t)warp * D + lane * 2));
        float2 r = make_float2(fmaf(acc.x, inv, z.x), fmaf(acc.y, inv, z.y));
        if (RELU) { r.x = fmaxf(r.x, 0.f); r.y = fmaxf(r.y, 0.f); }
        *(float2*)(O + (size_t)warp * D + lane * 2) = r;
    }
}

// ---------------- launch ----------------
extern "C" void kernel_launch(void* const* d_in, const int* in_sizes, int n_in,
                              void* d_out, int out_size) {
    const float* X = nullptr;
    const int*   ei = nullptr;
    const float* Wl1 = nullptr, *Wr1 = nullptr;
    const float* Wl2 = nullptr, *Wr2 = nullptr;
    const float* b1 = nullptr, *b2 = nullptr;

    for (int i = 0; i < n_in; i++) {
        int sz = in_sizes[i];
        const void* p = d_in[i];
        if (sz == N_NODES * D_IN)      X = (const float*)p;
        else if (sz == 2 * N_EDGES)    ei = (const int*)p;
        else if (sz == D_HID * D_IN)   { if (!Wl1) Wl1 = (const float*)p; else Wr1 = (const float*)p; }
        else if (sz == D_OUTD * D_HID) { if (!Wl2) Wl2 = (const float*)p; else Wr2 = (const float*)p; }
        else if (sz == D_HID)          b1 = (const float*)p;
        else if (sz == D_OUTD)         b2 = (const float*)p;
    }
    float* out = (float*)d_out;

    const int TPB = 256;

    // CSR build (reused by both layers)
    detect_kernel<<<1, 1>>>(ei);
    zero_deg_kernel<<<(N_NODES + TPB - 1) / TPB, TPB>>>();
    deg_kernel<<<(N_EDGES + TPB - 1) / TPB, TPB>>>(ei);
    scanA_kernel<<<NBLK, SCAN_B>>>();
    scanB_kernel<<<1, 128>>>();
    scanC_kernel<<<NBLK, SCAN_B>>>();
    fill_kernel<<<(N_EDGES + TPB - 1) / TPB, TPB>>>(ei);

    // layer 1: concat cols = 256 -> 2 tiles of 128
    gemm_tc<1><<<dim3((N_NODES + 127) / 128, 2), TPB>>>(X, Wl1, Wr1, b1);
    agg_kernel<1><<<(N_NODES * 32 + TPB - 1) / TPB, TPB>>>(nullptr);

    // layer 2: concat cols = 128 -> 1 tile
    gemm_tc<2><<<dim3((N_NODES + 127) / 128, 1), TPB>>>(X, Wl2, Wr2, b2);
    agg_kernel<2><<<(N_NODES * 32 + TPB - 1) / TPB, TPB>>>(out);
}